// round 17
// baseline (speedup 1.0000x reference)
#include <cuda_runtime.h>
#include <math.h>
#include <stdint.h>

#define BB 64
#define MM 512
#define SS 1024
#define EE 128
#define CC 10000
#define MSPLIT 8
#define NSPLIT 32
#define KCHUNK (SS / NSPLIT)  /* 32 */
#define PREF 16
#define TILES5 625            /* 10000/16 exact: 16-col tiles, one block each */

// ---------------- scratch (device globals; no allocation) ----------------
__device__ __align__(16) float g_partial[BB * MSPLIT * SS];   // 2 MB
__device__ __align__(16) float g_gpart[2 * NSPLIT * BB * EE]; // 2 MB
__device__ __align__(16) float g_uafrag[BB * EE];             // A fragments, mma order
__device__ __align__(16) float g_logits[BB * CC];             // 2.56 MB (exp(logits))
__device__ __align__(16) float g_psum[BB * TILES5];
__device__ __align__(16) float g_dummy[PREF * 256];

// ---------------- kernel 1: reduce stories over M + prefetch ALL weights --------
// blocks [0, BB*MSPLIT): sum 64 m-rows over S, MLP=8 streaming loads.
// blocks [BB*MSPLIT, +PREF): pull W1/W2/queries/W3/W4 into L2 under k1's shadow.
__global__ void k1_reduce_stories(const float* __restrict__ stories,
                                  const float* __restrict__ queries,
                                  const float* __restrict__ W1,
                                  const float* __restrict__ W2,
                                  const float* __restrict__ W3,
                                  const float* __restrict__ W4) {
    int blk = blockIdx.x;
    int t = threadIdx.x;

    if (blk >= BB * MSPLIT) {  // ---- L2 prefetch blocks ----
        int lane = (blk - BB * MSPLIT) * 256 + t;  // 0..4095
        float s = 0.f;
        const float4* a = (const float4*)W1;       // 32768 float4
        for (int i = lane; i < 32768; i += PREF * 256) {
            float4 v = __ldcg(&a[i]); s += v.x + v.y + v.z + v.w;
        }
        a = (const float4*)W2;
        for (int i = lane; i < 32768; i += PREF * 256) {
            float4 v = __ldcg(&a[i]); s += v.x + v.y + v.z + v.w;
        }
        a = (const float4*)queries;                // 16384 float4
        for (int i = lane; i < 16384; i += PREF * 256) {
            float4 v = __ldcg(&a[i]); s += v.x + v.y + v.z + v.w;
        }
        a = (const float4*)W3;                     // 4096 float4
        for (int i = lane; i < 4096; i += PREF * 256) {
            float4 v = __ldcg(&a[i]); s += v.x + v.y + v.z + v.w;
        }
        a = (const float4*)W4;                     // 320000 float4
        for (int i = lane; i < 320000; i += PREF * 256) {
            float4 v = __ldcg(&a[i]); s += v.x + v.y + v.z + v.w;
        }
        g_dummy[lane] = s;
        return;
    }

    int b = blk / MSPLIT, ms = blk % MSPLIT;
    const float4* src =
        (const float4*)(stories + (size_t)(b * MM + ms * (MM / MSPLIT)) * SS);
    float4 a0 = make_float4(0.f, 0.f, 0.f, 0.f);
    float4 a1 = a0, a2 = a0, a3 = a0, a4 = a0, a5 = a0, a6 = a0, a7 = a0;
#pragma unroll
    for (int m = 0; m < MM / MSPLIT; m += 8) {
        float4 v0 = __ldcs(&src[(size_t)(m + 0) * (SS / 4) + t]);
        float4 v1 = __ldcs(&src[(size_t)(m + 1) * (SS / 4) + t]);
        float4 v2 = __ldcs(&src[(size_t)(m + 2) * (SS / 4) + t]);
        float4 v3 = __ldcs(&src[(size_t)(m + 3) * (SS / 4) + t]);
        float4 v4 = __ldcs(&src[(size_t)(m + 4) * (SS / 4) + t]);
        float4 v5 = __ldcs(&src[(size_t)(m + 5) * (SS / 4) + t]);
        float4 v6 = __ldcs(&src[(size_t)(m + 6) * (SS / 4) + t]);
        float4 v7 = __ldcs(&src[(size_t)(m + 7) * (SS / 4) + t]);
        a0.x += v0.x; a0.y += v0.y; a0.z += v0.z; a0.w += v0.w;
        a1.x += v1.x; a1.y += v1.y; a1.z += v1.z; a1.w += v1.w;
        a2.x += v2.x; a2.y += v2.y; a2.z += v2.z; a2.w += v2.w;
        a3.x += v3.x; a3.y += v3.y; a3.z += v3.z; a3.w += v3.w;
        a4.x += v4.x; a4.y += v4.y; a4.z += v4.z; a4.w += v4.w;
        a5.x += v5.x; a5.y += v5.y; a5.z += v5.z; a5.w += v5.w;
        a6.x += v6.x; a6.y += v6.y; a6.z += v6.z; a6.w += v6.w;
        a7.x += v7.x; a7.y += v7.y; a7.z += v7.z; a7.w += v7.w;
    }
    float4 r;
    r.x = ((a0.x + a1.x) + (a2.x + a3.x)) + ((a4.x + a5.x) + (a6.x + a7.x));
    r.y = ((a0.y + a1.y) + (a2.y + a3.y)) + ((a4.y + a5.y) + (a6.y + a7.y));
    r.z = ((a0.z + a1.z) + (a2.z + a3.z)) + ((a4.z + a5.z) + (a6.z + a7.z));
    r.w = ((a0.w + a1.w) + (a2.w + a3.w)) + ((a4.w + a5.w) + (a6.w + a7.w));
    ((float4*)g_partial)[(size_t)blk * (SS / 4) + t] = r;
}

// ---------------- kernel 3: u0 = queries@W1^T, o = ssum@W2^T (split-K x32) ------
__global__ void k3_gemm64(const float* __restrict__ queries,
                          const float* __restrict__ W1,
                          const float* __restrict__ W2) {
    int ks = blockIdx.x;
    int eh = blockIdx.y;
    int which = blockIdx.z;
    const float* W = which ? W2 : W1;
    int kbase = ks * KCHUNK;

    __shared__ __align__(16) float Xs[32][68];
    __shared__ __align__(16) float Ws[32][68];

    int tid = threadIdx.x;
    int tb = tid & 15, te = tid >> 4;
    int lrow = tid >> 3, lkq = tid & 7;

    float acc[16];
#pragma unroll
    for (int i = 0; i < 16; i++) acc[i] = 0.f;

    {
#pragma unroll
        for (int h = 0; h < 2; h++) {
            int row = lrow + 32 * h;
            float4 xv;
            if (which == 0) {
                xv = *(const float4*)&queries[(size_t)row * SS + kbase + lkq * 4];
            } else {
                xv = make_float4(0.f, 0.f, 0.f, 0.f);
#pragma unroll
                for (int msp = 0; msp < MSPLIT; msp++) {
                    float4 v = *(const float4*)&g_partial[
                        (size_t)(row * MSPLIT + msp) * SS + kbase + lkq * 4];
                    xv.x += v.x; xv.y += v.y; xv.z += v.z; xv.w += v.w;
                }
            }
            float4 wv = *(const float4*)&W[(size_t)(eh * 64 + row) * SS + kbase + lkq * 4];
            Xs[lkq * 4 + 0][row] = xv.x; Xs[lkq * 4 + 1][row] = xv.y;
            Xs[lkq * 4 + 2][row] = xv.z; Xs[lkq * 4 + 3][row] = xv.w;
            Ws[lkq * 4 + 0][row] = wv.x; Ws[lkq * 4 + 1][row] = wv.y;
            Ws[lkq * 4 + 2][row] = wv.z; Ws[lkq * 4 + 3][row] = wv.w;
        }
        __syncthreads();
#pragma unroll
        for (int k = 0; k < 32; k++) {
            float4 xv = *(const float4*)&Xs[k][tb * 4];
            float4 wv = *(const float4*)&Ws[k][te * 4];
            acc[0]  += xv.x * wv.x; acc[1]  += xv.x * wv.y;
            acc[2]  += xv.x * wv.z; acc[3]  += xv.x * wv.w;
            acc[4]  += xv.y * wv.x; acc[5]  += xv.y * wv.y;
            acc[6]  += xv.y * wv.z; acc[7]  += xv.y * wv.w;
            acc[8]  += xv.z * wv.x; acc[9]  += xv.z * wv.y;
            acc[10] += xv.z * wv.z; acc[11] += xv.z * wv.w;
            acc[12] += xv.w * wv.x; acc[13] += xv.w * wv.y;
            acc[14] += xv.w * wv.z; acc[15] += xv.w * wv.w;
        }
    }
#pragma unroll
    for (int i = 0; i < 4; i++)
#pragma unroll
        for (int j = 0; j < 4; j++)
            g_gpart[(size_t)((which * NSPLIT + ks) * BB + tb * 4 + i) * EE +
                    eh * 64 + te * 4 + j] = acc[i * 4 + j];
}

// ---------------- kernel 4: split-K combine + hops + norm; writes A-frags -------
// Final u written as tf32-rounded mma A-fragments (m16n8k8 layout):
// a0=(g,t) a1=(g+8,t) a2=(g,t+4) a3=(g+8,t+4), lane = g*4+t.
__global__ void k4_hops(const float* __restrict__ W3) {
    __shared__ float us[EE];
    __shared__ float red[4];
    int b = blockIdx.x;
    int f = threadIdx.x;

    float4 w[32];
    const float4* wrow = (const float4*)(W3 + (size_t)f * EE);
#pragma unroll
    for (int q = 0; q < 32; q++) w[q] = __ldcg(&wrow[q]);

    float u = 0.f, o = 0.f;
#pragma unroll
    for (int ks = 0; ks < NSPLIT; ks++) {
        u += g_gpart[(size_t)(ks * BB + b) * EE + f];
        o += g_gpart[(size_t)((NSPLIT + ks) * BB + b) * EE + f];
    }
    us[f] = u;
    __syncthreads();

    float vout = 0.f;
    const float4* us4 = (const float4*)us;
    for (int hop = 0; hop < 3; hop++) {
        float v0 = 0.f, v1 = 0.f, v2 = 0.f, v3 = 0.f;
#pragma unroll
        for (int q = 0; q < 32; q++) {
            float4 uu = us4[q];
            v0 += w[q].x * uu.x;
            v1 += w[q].y * uu.y;
            v2 += w[q].z * uu.z;
            v3 += w[q].w * uu.w;
        }
        float v = o + ((v0 + v1) + (v2 + v3));
        float s = v * v;
#pragma unroll
        for (int off = 16; off; off >>= 1)
            s += __shfl_xor_sync(0xffffffffu, s, off);
        if ((f & 31) == 0) red[f >> 5] = s;
        __syncthreads();
        float tot = (red[0] + red[1]) + (red[2] + red[3]);
        float nrm = fmaxf(sqrtf(tot), 1e-12f);
        vout = v / nrm;
        us[f] = vout;
        __syncthreads();
    }

    // scatter into mma A-fragment order, tf32-rounded
    int wm = b >> 4, r = b & 15, rh = r >> 3, g = r & 7;
    int kstep = f >> 3, kt = f & 7, ch = kt >> 2, t = kt & 3;
    uint32_t bits;
    asm("cvt.rna.tf32.f32 %0, %1;" : "=r"(bits) : "f"(vout));
    g_uafrag[(size_t)(((wm * 16 + kstep) * 32 + (g * 4 + t)) * 4) + (ch * 2 + rh)] =
        __uint_as_float(bits);
}

// ---------------- kernel 5: exp(u @ W4^T) via tf32 mma, A direct from L1/L2 -----
// grid = 625 (64b x 16c tile, K=128 = 16 mma steps), block = 256 (8 warps =
// 4 m-strips x 2 n8-halves). A fragments identical per block -> __ldg direct.
// W tile in 8.6 KB static smem. __launch_bounds__(256, 4): reg cap 64 so ptxas
// can hoist/pipeline the 16 independent LDG pairs (regs=32 was serializing the
// mainloop on L2 latency). 4 blocks/SM = 32 warps, still latency-tolerant.
#define WP5 132
__global__ void __launch_bounds__(256, 4) k5_logits(const float* __restrict__ W4) {
    __shared__ __align__(16) float Ws[16 * WP5];
    __shared__ float rpart[2 * 66];

    int tid = threadIdx.x;
    int c0 = blockIdx.x * 16;

    // ---- stage W4 tile [c][k] with tf32 rounding (16 cols, 2 float4/thread) ----
    {
        int c = tid >> 4, h = tid & 15;    // col 0..15, k-16th 0..15
        const float4* wsrc = (const float4*)(W4 + (size_t)(c0 + c) * EE);
#pragma unroll
        for (int i = 0; i < 2; i++) {
            int q = h * 2 + i;             // k-quad 0..31
            float4 wv = wsrc[q];
            uint32_t q0, q1, q2, q3;
            asm("cvt.rna.tf32.f32 %0, %1;" : "=r"(q0) : "f"(wv.x));
            asm("cvt.rna.tf32.f32 %0, %1;" : "=r"(q1) : "f"(wv.y));
            asm("cvt.rna.tf32.f32 %0, %1;" : "=r"(q2) : "f"(wv.z));
            asm("cvt.rna.tf32.f32 %0, %1;" : "=r"(q3) : "f"(wv.w));
            *(float4*)&Ws[c * WP5 + q * 4] =
                make_float4(__uint_as_float(q0), __uint_as_float(q1),
                            __uint_as_float(q2), __uint_as_float(q3));
        }
    }
    __syncthreads();

    int w = tid >> 5, l = tid & 31;
    int wm = w & 3, wn = w >> 2;           // 4 m-strips x 2 n8-halves
    int g = l >> 2, t = l & 3;

    const float4* afr = (const float4*)g_uafrag;

    float acc[4];
    acc[0] = acc[1] = acc[2] = acc[3] = 0.f;

#pragma unroll
    for (int ks = 0; ks < 16; ks++) {
        float4 av = __ldg(&afr[(wm * 16 + ks) * 32 + l]);
        uint32_t a0 = __float_as_uint(av.x), a1 = __float_as_uint(av.y);
        uint32_t a2 = __float_as_uint(av.z), a3 = __float_as_uint(av.w);
        int cc = wn * 8 + g;
        uint32_t b0 = __float_as_uint(Ws[cc * WP5 + ks * 8 + t]);
        uint32_t b1 = __float_as_uint(Ws[cc * WP5 + ks * 8 + t + 4]);
        asm volatile(
            "mma.sync.aligned.m16n8k8.row.col.f32.tf32.tf32.f32 "
            "{%0,%1,%2,%3}, {%4,%5,%6,%7}, {%8,%9}, {%0,%1,%2,%3};"
            : "+f"(acc[0]), "+f"(acc[1]), "+f"(acc[2]), "+f"(acc[3])
            : "r"(a0), "r"(a1), "r"(a2), "r"(a3), "r"(b0), "r"(b1));
    }

    // ---- epilogue: exp, float2 stores, row partial sums ----
    int row0 = wm * 16 + g, row1 = row0 + 8;
    int cc = c0 + wn * 8 + 2 * t;
    float e0 = __expf(acc[0]);
    float e1 = __expf(acc[1]);
    float e2 = __expf(acc[2]);
    float e3 = __expf(acc[3]);
    *(float2*)&g_logits[(size_t)row0 * CC + cc] = make_float2(e0, e1);
    *(float2*)&g_logits[(size_t)row1 * CC + cc] = make_float2(e2, e3);
    float s0 = e0 + e1;
    float s1 = e2 + e3;
    s0 += __shfl_xor_sync(0xffffffffu, s0, 1);
    s0 += __shfl_xor_sync(0xffffffffu, s0, 2);
    s1 += __shfl_xor_sync(0xffffffffu, s1, 1);
    s1 += __shfl_xor_sync(0xffffffffu, s1, 2);
    if (t == 0) {
        rpart[wn * 66 + row0] = s0;
        rpart[wn * 66 + row1] = s1;
    }
    __syncthreads();
    if (tid < BB) {
        g_psum[(size_t)tid * TILES5 + blockIdx.x] =
            rpart[tid] + rpart[66 + tid];
    }
}

// ---------------- kernel 6: scale exp by 1/rowsum ----------------
__global__ void k6_scale(float* __restrict__ out) {
    int b = blockIdx.x, ch = blockIdx.y, t = threadIdx.x;
    __shared__ float sred[8];
    const float* prow = g_psum + (size_t)b * TILES5;
    float p = prow[t] + prow[t + 256];              // 0..511
    if (t < TILES5 - 512) p += prow[t + 512];       // 512..624
#pragma unroll
    for (int off = 16; off; off >>= 1)
        p += __shfl_xor_sync(0xffffffffu, p, off);
    if ((t & 31) == 0) sred[t >> 5] = p;
    __syncthreads();
    float tot = ((sred[0] + sred[1]) + (sred[2] + sred[3])) +
                ((sred[4] + sred[5]) + (sred[6] + sred[7]));
    float inv = 1.0f / tot;

    int i = ch * 250 + t;
    if (t < 250) {
        float4 v = __ldcs(&((const float4*)(g_logits + (size_t)b * CC))[i]);
        float4 r;
        r.x = v.x * inv; r.y = v.y * inv; r.z = v.z * inv; r.w = v.w * inv;
        ((float4*)(out + (size_t)b * CC))[i] = r;
    }
}

// ---------------- launch ----------------
extern "C" void kernel_launch(void* const* d_in, const int* in_sizes, int n_in,
                              void* d_out, int out_size) {
    const float* stories = (const float*)d_in[0];
    const float* queries = (const float*)d_in[1];
    const float* W1 = (const float*)d_in[2];
    const float* W2 = (const float*)d_in[3];
    const float* W3 = (const float*)d_in[4];
    const float* W4 = (const float*)d_in[5];
    float* out = (float*)d_out;

    k1_reduce_stories<<<BB * MSPLIT + PREF, 256>>>(stories, queries, W1, W2, W3, W4);
    dim3 g3(NSPLIT, 2, 2);
    k3_gemm64<<<g3, 256>>>(queries, W1, W2);
    k4_hops<<<BB, EE>>>(W3);
    k5_logits<<<TILES5, 256>>>(W4);
    dim3 g6(BB, 10);
    k6_scale<<<g6, 256>>>(out);
}